// round 16
// baseline (speedup 1.0000x reference)
#include <cuda_runtime.h>
#include <cuda_fp16.h>
#include <cstdint>

// Problem constants
#define NM 100000
#define NT 100000
#define NE 400000
#define DD 128
#define K2 256
#define KP2 (K2 / 2)
#define NMAX 100000
#define AGG4 ((size_t)NMAX * DD / 4)

#define CDIV(a,b) (((a)+(b)-1)/(b))

// ---------------- scratch ----------------
__device__ float4 g_agg_t[2 * AGG4];
__device__ float4 g_agg_m[2 * AGG4];
__device__ float4 g_bm0[AGG4];
__device__ float4 g_bm1[AGG4];
__device__ float4 g_bt0[AGG4];
__device__ float4 g_bt1[AGG4];
__device__ float4 g_inv_t[NT / 4];
__device__ float4 g_inv_m[NM / 4];
__device__ float4 g_Bext[3 * 2 * KP2 * DD / 4];  // half2 pairs [lt][kp][j]
__device__ int    g_e32_mt[2 * NE];
__device__ int    g_e32_tm[2 * NE];
__device__ int    g_is32 = 0;

__device__ __forceinline__ uint32_t smem_u32(const void* p) {
    uint32_t a;
    asm("{ .reg .u64 t; cvta.to.shared.u64 t, %1; cvt.u32.u64 %0, t; }" : "=r"(a) : "l"(p));
    return a;
}
__device__ __forceinline__ uint32_t pack_h2(float lo, float hi) {
    half2 h = __floats2half2_rn(lo, hi);
    return *(uint32_t*)&h;
}
#define MBAR_INIT(a, n) asm volatile("mbarrier.init.shared.b64 [%0], %1;" :: "r"(a), "r"(n) : "memory")
#define MBAR_EXPECT(a, b) asm volatile("mbarrier.arrive.expect_tx.shared.b64 _, [%0], %1;" :: "r"(a), "r"(b) : "memory")
#define MBAR_WAIT(a, ph) do { \
    uint32_t _m = (a); uint32_t _p = (ph); uint32_t _d; \
    asm volatile("{\n\t.reg .pred p;\n\t" \
        "mbarrier.try_wait.parity.acquire.cta.shared::cta.b64 p, [%1], %2;\n\t" \
        "selp.b32 %0, 1, 0, p;\n\t}" : "=r"(_d) : "r"(_m), "r"(_p) : "memory"); \
    if (!_d) { \
        asm volatile("{\n\t.reg .pred P1;\n\tWL_%=:\n\t" \
            "mbarrier.try_wait.parity.acquire.cta.shared::cta.b64 P1, [%0], %1, 0x989680;\n\t" \
            "@P1 bra.uni WD_%=;\n\tbra.uni WL_%=;\n\tWD_%=:\n\t}" \
            :: "r"(_m), "r"(_p) : "memory"); \
    } } while (0)

// ---------------- preproc kernels ----------------
__global__ void detect_kernel(const unsigned* __restrict__ p) {
    int i = blockIdx.x * blockDim.x + threadIdx.x;
    unsigned v = 0;
    for (int w = i * 2 + 1; w < 2 * NE; w += gridDim.x * blockDim.x * 2) v |= p[w];
    if (__syncthreads_or(v != 0) && threadIdx.x == 0) atomicExch(&g_is32, 1);
}
__global__ void convert_count(const void* __restrict__ e, int* __restrict__ out,
                              float* __restrict__ cnt) {
    int i = blockIdx.x * blockDim.x + threadIdx.x;
    if (i >= 2 * NE) return;
    int v;
    if (g_is32) v = ((const int*)e)[i];
    else        v = (int)((const long long*)e)[i];
    v = min(max(v, 0), NMAX - 1);
    out[i] = v;
    if (i >= NE) atomicAdd(&cnt[v], 1.0f);
}
__global__ void invert_kernel(float* __restrict__ c, int n) {
    int i = blockIdx.x * blockDim.x + threadIdx.x;
    if (i < n) c[i] = 1.0f / fmaxf(c[i], 1.0f);
}
__global__ void zero4(float4* a, int na, float4* b, int nb,
                      float4* c, int nc, float4* d, int nd) {
    int i = blockIdx.x * blockDim.x + threadIdx.x;
    int stride = gridDim.x * blockDim.x;
    float4 z = make_float4(0.f, 0.f, 0.f, 0.f);
    for (int k = i; k < na; k += stride) a[k] = z;
    for (int k = i; k < nb; k += stride) b[k] = z;
    for (int k = i; k < nc; k += stride) c[k] = z;
    for (int k = i; k < nd; k += stride) d[k] = z;
}
__global__ void zero_two(float4* p0, int n0, float4* p1, int n1) {
    int i = blockIdx.x * blockDim.x + threadIdx.x;
    int stride = gridDim.x * blockDim.x;
    float4 z = make_float4(0.f, 0.f, 0.f, 0.f);
    for (int k = i; k < n0; k += stride) p0[k] = z;
    for (int k = i; k < n1; k += stride) p1[k] = z;
}
__global__ void zero_kernel(float4* p, int n4) {
    int i = blockIdx.x * blockDim.x + threadIdx.x;
    int stride = gridDim.x * blockDim.x;
    float4 z = make_float4(0.f, 0.f, 0.f, 0.f);
    for (; i < n4; i += stride) p[i] = z;
}
__global__ void prep_weights(const float* __restrict__ Wl,
                             const float* __restrict__ Wr,
                             uint32_t* __restrict__ Bext) {
    int i = blockIdx.x * blockDim.x + threadIdx.x;
    if (i >= 3 * 2 * KP2 * DD) return;
    int j  = i % DD;
    int kp = (i / DD) % KP2;
    int lt = i / (DD * KP2);
    int k0 = 2 * kp;
    float v0, v1;
    if (k0 < DD) {
        v0 = Wl[((size_t)lt * DD + j) * DD + k0];
        v1 = Wl[((size_t)lt * DD + j) * DD + k0 + 1];
    } else {
        v0 = Wr[((size_t)lt * DD + j) * DD + (k0 - DD)];
        v1 = Wr[((size_t)lt * DD + j) * DD + (k0 - DD + 1)];
    }
    Bext[i] = pack_h2(v0, v1);
}

// ---------------- scatter: TMA bulk gather -> TMA bulk reduce --------------
// Per warp: EPW edges. Lanes 0..EPW-1 each issue one 512B bulk-load
// (global->smem, mbarrier completion), wait, then one bulk-reduce
// (smem->global add.f32). No LDG/STS on the data path at all.
#define EPW 8
__global__ void __launch_bounds__(256)
scatter_bulk(const float* __restrict__ xsrc, const int* __restrict__ edge,
             float* __restrict__ agg) {
    __shared__ __align__(16) float smem[8][EPW][DD];   // 32KB
    __shared__ __align__(8) uint64_t mbar[8];
    const int wInB = threadIdx.x >> 5;
    const int lane = threadIdx.x & 31;
    const int gw = (blockIdx.x * blockDim.x + threadIdx.x) >> 5;
    const int base = gw * EPW;
    if (base >= NE) return;
    const int nE = min(EPW, NE - base);
    const uint32_t mb = smem_u32(&mbar[wInB]);

    if (lane == 0) {
        MBAR_INIT(mb, 1);
        asm volatile("fence.proxy.async.shared::cta;" ::: "memory");
        MBAR_EXPECT(mb, (uint32_t)(nE * DD * 4));
    }
    __syncwarp();
    if (lane < nE) {
        int src = edge[base + lane];
        const float* gp = xsrc + (size_t)src * DD;
        uint32_t sa = smem_u32(&smem[wInB][lane][0]);
        asm volatile(
            "cp.async.bulk.shared::cta.global.mbarrier::complete_tx::bytes "
            "[%0], [%1], %2, [%3];"
            :: "r"(sa), "l"(gp), "r"(DD * 4), "r"(mb) : "memory");
    }
    if (lane < nE) {
        MBAR_WAIT(mb, 0);
        int dst = edge[NE + base + lane];
        float* gp = agg + (size_t)dst * DD;
        uint32_t sa = smem_u32(&smem[wInB][lane][0]);
        asm volatile(
            "cp.reduce.async.bulk.global.shared::cta.bulk_group.add.f32 "
            "[%0], [%1], %2;" :: "l"(gp), "r"(sa), "r"(DD * 4) : "memory");
        asm volatile("cp.async.bulk.commit_group;" ::: "memory");
        asm volatile("cp.async.bulk.wait_group 0;" ::: "memory");
    }
}

// ---------------- fp16 mma.sync GEMM (m16n8k16, fp32 accum; R15-proven) ----
__global__ void __launch_bounds__(256)
gemm_sage_tc(const float* __restrict__ Aagg, const float* __restrict__ inv,
             const float* __restrict__ Xdst, const uint32_t* __restrict__ B,
             const float* __restrict__ bias, float* __restrict__ Cout,
             int nRows, int relu) {
    __shared__ uint32_t As[128][20];
    __shared__ uint32_t Bs[16][136];

    const int tid  = threadIdx.x;
    const int wid  = tid >> 5;
    const int lane = tid & 31;
    const int g    = lane >> 2;
    const int t    = lane & 3;
    const int m0   = (wid & 1) * 64;
    const int n0   = (wid >> 1) * 32;
    const int rowBase = blockIdx.x * 128;

    float acc[4][4][4];
#pragma unroll
    for (int im = 0; im < 4; im++)
#pragma unroll
        for (int in = 0; in < 4; in++)
#pragma unroll
            for (int q = 0; q < 4; q++) acc[im][in][q] = 0.f;

    for (int kt = 0; kt < K2; kt += 32) {
        const int ktp = kt >> 1;
#pragma unroll
        for (int p = 0; p < 4; p++) {
            int f = tid + p * 256;
            int r = f >> 3;
            int q = f & 7;
            int gr = rowBase + r;
            if (gr >= nRows) gr = nRows - 1;
            int kg = kt + q * 4;
            float s;
            const float* src;
            if (kg < DD) { src = Aagg + (size_t)gr * DD + kg; s = inv[gr]; }
            else         { src = Xdst + (size_t)gr * DD + (kg - DD); s = 1.0f; }
            float4 v = *(const float4*)src;
            As[r][q * 2 + 0] = pack_h2(v.x * s, v.y * s);
            As[r][q * 2 + 1] = pack_h2(v.z * s, v.w * s);
        }
#pragma unroll
        for (int p = 0; p < 2; p++) {
            int f = tid + p * 256;
            int kp = f >> 5;
            int c4 = f & 31;
            *(uint4*)&Bs[kp][c4 * 4] =
                *(const uint4*)(B + (size_t)(ktp + kp) * DD + c4 * 4);
        }
        __syncthreads();

#pragma unroll
        for (int ks2 = 0; ks2 < 16; ks2 += 8) {
            uint32_t a[4][4], b[4][2];
#pragma unroll
            for (int im = 0; im < 4; im++) {
                int rm = m0 + im * 16 + g;
                a[im][0] = As[rm][ks2 + t];
                a[im][1] = As[rm + 8][ks2 + t];
                a[im][2] = As[rm][ks2 + 4 + t];
                a[im][3] = As[rm + 8][ks2 + 4 + t];
            }
#pragma unroll
            for (int in = 0; in < 4; in++) {
                int cn = n0 + in * 8 + g;
                b[in][0] = Bs[ks2 + t][cn];
                b[in][1] = Bs[ks2 + 4 + t][cn];
            }
#pragma unroll
            for (int im = 0; im < 4; im++)
#pragma unroll
                for (int in = 0; in < 4; in++) {
                    asm volatile(
                        "mma.sync.aligned.m16n8k16.row.col.f32.f16.f16.f32 "
                        "{%0,%1,%2,%3}, {%4,%5,%6,%7}, {%8,%9}, {%0,%1,%2,%3};"
                        : "+f"(acc[im][in][0]), "+f"(acc[im][in][1]),
                          "+f"(acc[im][in][2]), "+f"(acc[im][in][3])
                        : "r"(a[im][0]), "r"(a[im][1]), "r"(a[im][2]), "r"(a[im][3]),
                          "r"(b[in][0]), "r"(b[in][1]));
                }
        }
        __syncthreads();
    }

#pragma unroll
    for (int in = 0; in < 4; in++) {
        int col = n0 + in * 8 + 2 * t;
        float b0 = bias[col], b1 = bias[col + 1];
#pragma unroll
        for (int im = 0; im < 4; im++) {
            int r0 = rowBase + m0 + im * 16 + g;
            float v0 = acc[im][in][0] + b0;
            float v1 = acc[im][in][1] + b1;
            float v2 = acc[im][in][2] + b0;
            float v3 = acc[im][in][3] + b1;
            if (relu) {
                v0 = fmaxf(v0, 0.f); v1 = fmaxf(v1, 0.f);
                v2 = fmaxf(v2, 0.f); v3 = fmaxf(v3, 0.f);
            }
            if (r0 < nRows)
                *(float2*)(Cout + (size_t)r0 * DD + col) = make_float2(v0, v1);
            if (r0 + 8 < nRows)
                *(float2*)(Cout + (size_t)(r0 + 8) * DD + col) = make_float2(v2, v3);
        }
    }
}

// ---------------- launch ----------------
extern "C" void kernel_launch(void* const* d_in, const int* in_sizes, int n_in,
                              void* d_out, int out_size) {
    static bool s_init = false;
    static cudaStream_t sM;
    static cudaEvent_t evZ, evDet, evPrep, evZ1, evGT[3], evGM[3];
    if (!s_init) {
        cudaStreamCreateWithFlags(&sM, cudaStreamNonBlocking);
        cudaEventCreateWithFlags(&evZ, cudaEventDisableTiming);
        cudaEventCreateWithFlags(&evDet, cudaEventDisableTiming);
        cudaEventCreateWithFlags(&evPrep, cudaEventDisableTiming);
        cudaEventCreateWithFlags(&evZ1, cudaEventDisableTiming);
        for (int i = 0; i < 3; i++) {
            cudaEventCreateWithFlags(&evGT[i], cudaEventDisableTiming);
            cudaEventCreateWithFlags(&evGM[i], cudaEventDisableTiming);
        }
        s_init = true;
    }

    const float* x_m = (const float*)d_in[0];
    const float* x_t = (const float*)d_in[1];
    const float* Wl  = (const float*)d_in[2];
    const float* bl  = (const float*)d_in[3];
    const float* Wr  = (const float*)d_in[4];
    const void*  e_mt = d_in[5];
    const void*  e_tm = d_in[6];
    float* out = (float*)d_out;

    float *agg_t, *agg_m, *bm0, *bm1, *bt0, *bt1, *inv_t, *inv_m;
    uint32_t* Bext;
    int *e32_mt, *e32_tm;
    cudaGetSymbolAddress((void**)&agg_t, g_agg_t);
    cudaGetSymbolAddress((void**)&agg_m, g_agg_m);
    cudaGetSymbolAddress((void**)&bm0, g_bm0);
    cudaGetSymbolAddress((void**)&bm1, g_bm1);
    cudaGetSymbolAddress((void**)&bt0, g_bt0);
    cudaGetSymbolAddress((void**)&bt1, g_bt1);
    cudaGetSymbolAddress((void**)&inv_t, g_inv_t);
    cudaGetSymbolAddress((void**)&inv_m, g_inv_m);
    cudaGetSymbolAddress((void**)&Bext, g_Bext);
    cudaGetSymbolAddress((void**)&e32_mt, g_e32_mt);
    cudaGetSymbolAddress((void**)&e32_tm, g_e32_tm);

    const int scatterBlocks = CDIV(NE, 8 * EPW);   // 8 warps/block * EPW edges
    const int agg4 = (int)AGG4;
    float* aggT[2] = { agg_t, agg_t + AGG4 * 4 };
    float* aggM[2] = { agg_m, agg_m + AGG4 * 4 };
    float* out_m = out;
    float* out_t = out + (size_t)NM * DD;

    // ---- origin stream (track chain). Launch index 3 = scatter_bulk (ncu) --
    zero4<<<4096, 256>>>((float4*)inv_t, NT / 4, (float4*)inv_m, NM / 4,
                         (float4*)aggT[0], agg4, (float4*)aggM[0], agg4);
    cudaEventRecord(evZ, 0);
    detect_kernel<<<256, 256>>>((const unsigned*)e_mt);
    cudaEventRecord(evDet, 0);
    convert_count<<<CDIV(2 * NE, 256), 256>>>(e_mt, e32_mt, (float*)inv_t);
    scatter_bulk<<<scatterBlocks, 256>>>(x_m, e32_mt, aggT[0]);
    invert_kernel<<<CDIV(NT, 256), 256>>>((float*)inv_t, NT);
    prep_weights<<<CDIV(3 * 2 * KP2 * DD, 256), 256>>>(Wl, Wr, Bext);
    cudaEventRecord(evPrep, 0);
    gemm_sage_tc<<<CDIV(NT, 128), 256>>>(
        aggT[0], (float*)inv_t, x_t, Bext + (size_t)0 * KP2 * DD,
        bl + (size_t)0 * DD, bt0, NT, 1);
    cudaEventRecord(evGT[0], 0);
    zero_kernel<<<2048, 256>>>((float4*)aggT[0], agg4);

    // ---- stream M (musician chain) ----
    cudaStreamWaitEvent(sM, evDet, 0);
    cudaStreamWaitEvent(sM, evZ, 0);
    convert_count<<<CDIV(2 * NE, 256), 256, 0, sM>>>(e_tm, e32_tm, (float*)inv_m);
    invert_kernel<<<CDIV(NM, 256), 256, 0, sM>>>((float*)inv_m, NM);
    zero_two<<<2048, 256, 0, sM>>>((float4*)aggT[1], agg4, (float4*)aggM[1], agg4);
    cudaEventRecord(evZ1, sM);
    scatter_bulk<<<scatterBlocks, 256, 0, sM>>>(x_t, e32_tm, aggM[0]);
    cudaStreamWaitEvent(sM, evPrep, 0);
    gemm_sage_tc<<<CDIV(NM, 128), 256, 0, sM>>>(
        aggM[0], (float*)inv_m, x_m, Bext + (size_t)1 * KP2 * DD,
        bl + (size_t)1 * DD, bm0, NM, 1);
    cudaEventRecord(evGM[0], sM);
    zero_kernel<<<2048, 256, 0, sM>>>((float4*)aggM[0], agg4);

    const float* xm_cur = bm0;
    const float* xt_cur = bt0;

    for (int layer = 1; layer < 3; layer++) {
        const int b = layer & 1;
        float* xt_next = (layer == 2) ? out_t : bt1;
        float* xm_next = (layer == 2) ? out_m : bm1;
        int relu = (layer < 2) ? 1 : 0;

        cudaStreamWaitEvent(0, evGM[layer - 1], 0);
        if (layer == 1) cudaStreamWaitEvent(0, evZ1, 0);
        scatter_bulk<<<scatterBlocks, 256>>>(xm_cur, e32_mt, aggT[b]);
        gemm_sage_tc<<<CDIV(NT, 128), 256>>>(
            aggT[b], (float*)inv_t, xt_cur,
            Bext + (size_t)(layer * 2 + 0) * KP2 * DD,
            bl + (size_t)(layer * 2 + 0) * DD,
            xt_next, NT, relu);
        cudaEventRecord(evGT[layer], 0);

        cudaStreamWaitEvent(sM, evGT[layer - 1], 0);
        scatter_bulk<<<scatterBlocks, 256, 0, sM>>>(xt_cur, e32_tm, aggM[b]);
        gemm_sage_tc<<<CDIV(NM, 128), 256, 0, sM>>>(
            aggM[b], (float*)inv_m, xm_cur,
            Bext + (size_t)(layer * 2 + 1) * KP2 * DD,
            bl + (size_t)(layer * 2 + 1) * DD,
            xm_next, NM, relu);
        cudaEventRecord(evGM[layer], sM);

        xm_cur = xm_next;
        xt_cur = xt_next;
    }

    cudaStreamWaitEvent(0, evGM[2], 0);
}

// round 17
// speedup vs baseline: 1.4392x; 1.4392x over previous
#include <cuda_runtime.h>
#include <cuda_fp16.h>
#include <cstdint>

// Problem constants
#define NM 100000
#define NT 100000
#define NE 400000
#define DD 128
#define K2 256
#define KP2 (K2 / 2)
#define NMAX 100000
#define AGGH4 ((size_t)NMAX * DD / 8)   // float4 units for a half buffer

#define CDIV(a,b) (((a)+(b)-1)/(b))

// ---------------- scratch (half buffers declared as float4 for alignment) --
__device__ float4 g_x16_m[AGGH4];
__device__ float4 g_x16_t[AGGH4];
__device__ float4 g_agg_t[2 * AGGH4];
__device__ float4 g_agg_m[2 * AGGH4];
__device__ float4 g_bm0[AGGH4];
__device__ float4 g_bm1[AGGH4];
__device__ float4 g_bt0[AGGH4];
__device__ float4 g_bt1[AGGH4];
__device__ float4 g_inv_t[NT / 4];
__device__ float4 g_inv_m[NM / 4];
__device__ float4 g_Bext[3 * 2 * KP2 * DD / 4];  // half2 pairs [lt][kp][j]
__device__ int    g_e32_mt[2 * NE];
__device__ int    g_e32_tm[2 * NE];
__device__ int    g_is32 = 0;

__device__ __forceinline__ uint32_t smem_u32(const void* p) {
    uint32_t a;
    asm("{ .reg .u64 t; cvta.to.shared.u64 t, %1; cvt.u32.u64 %0, t; }" : "=r"(a) : "l"(p));
    return a;
}
__device__ __forceinline__ uint32_t pack_h2(float lo, float hi) {
    half2 h = __floats2half2_rn(lo, hi);
    return *(uint32_t*)&h;
}
#define MBAR_INIT(a, n) asm volatile("mbarrier.init.shared.b64 [%0], %1;" :: "r"(a), "r"(n) : "memory")
#define MBAR_EXPECT(a, b) asm volatile("mbarrier.arrive.expect_tx.shared.b64 _, [%0], %1;" :: "r"(a), "r"(b) : "memory")
#define MBAR_WAIT(a, ph) do { \
    uint32_t _m = (a); uint32_t _p = (ph); uint32_t _d; \
    asm volatile("{\n\t.reg .pred p;\n\t" \
        "mbarrier.try_wait.parity.acquire.cta.shared::cta.b64 p, [%1], %2;\n\t" \
        "selp.b32 %0, 1, 0, p;\n\t}" : "=r"(_d) : "r"(_m), "r"(_p) : "memory"); \
    if (!_d) { \
        asm volatile("{\n\t.reg .pred P1;\n\tWL_%=:\n\t" \
            "mbarrier.try_wait.parity.acquire.cta.shared::cta.b64 P1, [%0], %1, 0x989680;\n\t" \
            "@P1 bra.uni WD_%=;\n\tbra.uni WL_%=;\n\tWD_%=:\n\t}" \
            :: "r"(_m), "r"(_p) : "memory"); \
    } } while (0)

// ---------------- preproc ----------------
// Fused: zero inv_t/inv_m + zero agg buf0s + convert x_m/x_t to fp16
__global__ void prep_buffers(const float2* __restrict__ xm, const float2* __restrict__ xt,
                             half2* __restrict__ xm16, half2* __restrict__ xt16,
                             float4* __restrict__ invt, float4* __restrict__ invm,
                             float4* __restrict__ aggT0, float4* __restrict__ aggM0) {
    int i = blockIdx.x * blockDim.x + threadIdx.x;
    int stride = gridDim.x * blockDim.x;
    float4 z = make_float4(0.f, 0.f, 0.f, 0.f);
    for (int k = i; k < NT / 4; k += stride) invt[k] = z;
    for (int k = i; k < NM / 4; k += stride) invm[k] = z;
    for (int k = i; k < (int)AGGH4; k += stride) aggT0[k] = z;
    for (int k = i; k < (int)AGGH4; k += stride) aggM0[k] = z;
    for (int k = i; k < NM * DD / 2; k += stride) {
        float2 v = xm[k];
        xm16[k] = __floats2half2_rn(v.x, v.y);
    }
    for (int k = i; k < NT * DD / 2; k += stride) {
        float2 v = xt[k];
        xt16[k] = __floats2half2_rn(v.x, v.y);
    }
}
__global__ void detect_kernel(const unsigned* __restrict__ p) {
    int i = blockIdx.x * blockDim.x + threadIdx.x;
    unsigned v = 0;
    for (int w = i * 2 + 1; w < 2 * NE; w += gridDim.x * blockDim.x * 2) v |= p[w];
    if (__syncthreads_or(v != 0) && threadIdx.x == 0) atomicExch(&g_is32, 1);
}
__global__ void convert_count(const void* __restrict__ e, int* __restrict__ out,
                              float* __restrict__ cnt) {
    int i = blockIdx.x * blockDim.x + threadIdx.x;
    if (i >= 2 * NE) return;
    int v;
    if (g_is32) v = ((const int*)e)[i];
    else        v = (int)((const long long*)e)[i];
    v = min(max(v, 0), NMAX - 1);
    out[i] = v;
    if (i >= NE) atomicAdd(&cnt[v], 1.0f);
}
__global__ void invert_kernel(float* __restrict__ c, int n) {
    int i = blockIdx.x * blockDim.x + threadIdx.x;
    if (i < n) c[i] = 1.0f / fmaxf(c[i], 1.0f);
}
__global__ void zero_two(float4* p0, int n0, float4* p1, int n1) {
    int i = blockIdx.x * blockDim.x + threadIdx.x;
    int stride = gridDim.x * blockDim.x;
    float4 z = make_float4(0.f, 0.f, 0.f, 0.f);
    for (int k = i; k < n0; k += stride) p0[k] = z;
    for (int k = i; k < n1; k += stride) p1[k] = z;
}
__global__ void zero_kernel(float4* p, int n4) {
    int i = blockIdx.x * blockDim.x + threadIdx.x;
    int stride = gridDim.x * blockDim.x;
    float4 z = make_float4(0.f, 0.f, 0.f, 0.f);
    for (; i < n4; i += stride) p[i] = z;
}
__global__ void prep_weights(const float* __restrict__ Wl,
                             const float* __restrict__ Wr,
                             uint32_t* __restrict__ Bext) {
    int i = blockIdx.x * blockDim.x + threadIdx.x;
    if (i >= 3 * 2 * KP2 * DD) return;
    int j  = i % DD;
    int kp = (i / DD) % KP2;
    int lt = i / (DD * KP2);
    int k0 = 2 * kp;
    float v0, v1;
    if (k0 < DD) {
        v0 = Wl[((size_t)lt * DD + j) * DD + k0];
        v1 = Wl[((size_t)lt * DD + j) * DD + k0 + 1];
    } else {
        v0 = Wr[((size_t)lt * DD + j) * DD + (k0 - DD)];
        v1 = Wr[((size_t)lt * DD + j) * DD + (k0 - DD + 1)];
    }
    Bext[i] = pack_h2(v0, v1);
}

// ---------------- scatter (fp16): TMA bulk gather -> bulk reduce f16 -------
#define EPW 8
__global__ void __launch_bounds__(256)
scatter_bulk(const __half* __restrict__ xsrc, const int* __restrict__ edge,
             __half* __restrict__ agg) {
    __shared__ __align__(16) __half smem[8][EPW][DD];   // 16KB
    __shared__ __align__(8) uint64_t mbar[8];
    const int wInB = threadIdx.x >> 5;
    const int lane = threadIdx.x & 31;
    const int gw = (blockIdx.x * blockDim.x + threadIdx.x) >> 5;
    const int base = gw * EPW;
    if (base >= NE) return;
    const int nE = min(EPW, NE - base);
    const uint32_t mb = smem_u32(&mbar[wInB]);

    if (lane == 0) {
        MBAR_INIT(mb, 1);
        asm volatile("fence.proxy.async.shared::cta;" ::: "memory");
        MBAR_EXPECT(mb, (uint32_t)(nE * DD * 2));
    }
    __syncwarp();
    if (lane < nE) {
        int src = edge[base + lane];
        const __half* gp = xsrc + (size_t)src * DD;
        uint32_t sa = smem_u32(&smem[wInB][lane][0]);
        asm volatile(
            "cp.async.bulk.shared::cta.global.mbarrier::complete_tx::bytes "
            "[%0], [%1], %2, [%3];"
            :: "r"(sa), "l"(gp), "r"(DD * 2), "r"(mb) : "memory");
    }
    if (lane < nE) {
        MBAR_WAIT(mb, 0);
        int dst = edge[NE + base + lane];
        __half* gp = agg + (size_t)dst * DD;
        uint32_t sa = smem_u32(&smem[wInB][lane][0]);
        asm volatile(
            "cp.reduce.async.bulk.global.shared::cta.bulk_group.add.noftz.f16 "
            "[%0], [%1], %2;" :: "l"(gp), "r"(sa), "r"(DD * 2) : "memory");
        asm volatile("cp.async.bulk.commit_group;" ::: "memory");
        asm volatile("cp.async.bulk.wait_group 0;" ::: "memory");
    }
}

// ---------------- fp16 mma.sync GEMM (fp16 in, fp32 accum, out f32|f16) ----
__global__ void __launch_bounds__(256)
gemm_sage_tc(const __half* __restrict__ Aagg, const float* __restrict__ inv,
             const __half* __restrict__ Xdst, const uint32_t* __restrict__ B,
             const float* __restrict__ bias, void* __restrict__ Cout,
             int nRows, int relu, int outHalf) {
    __shared__ uint32_t As[128][20];
    __shared__ uint32_t Bs[16][136];

    const int tid  = threadIdx.x;
    const int wid  = tid >> 5;
    const int lane = tid & 31;
    const int g    = lane >> 2;
    const int t    = lane & 3;
    const int m0   = (wid & 1) * 64;
    const int n0   = (wid >> 1) * 32;
    const int rowBase = blockIdx.x * 128;

    float acc[4][4][4];
#pragma unroll
    for (int im = 0; im < 4; im++)
#pragma unroll
        for (int in = 0; in < 4; in++)
#pragma unroll
            for (int q = 0; q < 4; q++) acc[im][in][q] = 0.f;

    for (int kt = 0; kt < K2; kt += 32) {
        const int ktp = kt >> 1;
        // ---- A fill: 128 rows x 32 k (fp16 src, uint4 = 8 halves) ----
#pragma unroll
        for (int p = 0; p < 2; p++) {
            int f = tid + p * 256;     // 0..511
            int r = f >> 2;            // 0..127
            int q = f & 3;             // uint4 idx; k = q*8
            int gr = rowBase + r;
            if (gr >= nRows) gr = nRows - 1;
            int kg = kt + q * 8;
            const __half* src;
            float s;
            if (kg < DD) { src = Aagg + (size_t)gr * DD + kg; s = inv[gr]; }
            else         { src = Xdst + (size_t)gr * DD + (kg - DD); s = 1.0f; }
            uint4 v = *(const uint4*)src;
            uint32_t w[4] = { v.x, v.y, v.z, v.w };
#pragma unroll
            for (int u = 0; u < 4; u++) {
                float2 f2 = __half22float2(*(half2*)&w[u]);
                As[r][q * 4 + u] = pack_h2(f2.x * s, f2.y * s);
            }
        }
        // ---- B fill ----
#pragma unroll
        for (int p = 0; p < 2; p++) {
            int f = tid + p * 256;
            int kp = f >> 5;
            int c4 = f & 31;
            *(uint4*)&Bs[kp][c4 * 4] =
                *(const uint4*)(B + (size_t)(ktp + kp) * DD + c4 * 4);
        }
        __syncthreads();

#pragma unroll
        for (int ks2 = 0; ks2 < 16; ks2 += 8) {
            uint32_t a[4][4], b[4][2];
#pragma unroll
            for (int im = 0; im < 4; im++) {
                int rm = m0 + im * 16 + g;
                a[im][0] = As[rm][ks2 + t];
                a[im][1] = As[rm + 8][ks2 + t];
                a[im][2] = As[rm][ks2 + 4 + t];
                a[im][3] = As[rm + 8][ks2 + 4 + t];
            }
#pragma unroll
            for (int in = 0; in < 4; in++) {
                int cn = n0 + in * 8 + g;
                b[in][0] = Bs[ks2 + t][cn];
                b[in][1] = Bs[ks2 + 4 + t][cn];
            }
#pragma unroll
            for (int im = 0; im < 4; im++)
#pragma unroll
                for (int in = 0; in < 4; in++) {
                    asm volatile(
                        "mma.sync.aligned.m16n8k16.row.col.f32.f16.f16.f32 "
                        "{%0,%1,%2,%3}, {%4,%5,%6,%7}, {%8,%9}, {%0,%1,%2,%3};"
                        : "+f"(acc[im][in][0]), "+f"(acc[im][in][1]),
                          "+f"(acc[im][in][2]), "+f"(acc[im][in][3])
                        : "r"(a[im][0]), "r"(a[im][1]), "r"(a[im][2]), "r"(a[im][3]),
                          "r"(b[in][0]), "r"(b[in][1]));
                }
        }
        __syncthreads();
    }

#pragma unroll
    for (int in = 0; in < 4; in++) {
        int col = n0 + in * 8 + 2 * t;
        float b0 = bias[col], b1 = bias[col + 1];
#pragma unroll
        for (int im = 0; im < 4; im++) {
            int r0 = rowBase + m0 + im * 16 + g;
            float v0 = acc[im][in][0] + b0;
            float v1 = acc[im][in][1] + b1;
            float v2 = acc[im][in][2] + b0;
            float v3 = acc[im][in][3] + b1;
            if (relu) {
                v0 = fmaxf(v0, 0.f); v1 = fmaxf(v1, 0.f);
                v2 = fmaxf(v2, 0.f); v3 = fmaxf(v3, 0.f);
            }
            if (outHalf) {
                __half* CH = (__half*)Cout;
                if (r0 < nRows)
                    *(half2*)(CH + (size_t)r0 * DD + col) = __floats2half2_rn(v0, v1);
                if (r0 + 8 < nRows)
                    *(half2*)(CH + (size_t)(r0 + 8) * DD + col) = __floats2half2_rn(v2, v3);
            } else {
                float* CF = (float*)Cout;
                if (r0 < nRows)
                    *(float2*)(CF + (size_t)r0 * DD + col) = make_float2(v0, v1);
                if (r0 + 8 < nRows)
                    *(float2*)(CF + (size_t)(r0 + 8) * DD + col) = make_float2(v2, v3);
            }
        }
    }
}

// ---------------- launch ----------------
extern "C" void kernel_launch(void* const* d_in, const int* in_sizes, int n_in,
                              void* d_out, int out_size) {
    static bool s_init = false;
    static cudaStream_t sM;
    static cudaEvent_t evZ, evDet, evPrep, evZ1, evGT[3], evGM[3];
    if (!s_init) {
        cudaStreamCreateWithFlags(&sM, cudaStreamNonBlocking);
        cudaEventCreateWithFlags(&evZ, cudaEventDisableTiming);
        cudaEventCreateWithFlags(&evDet, cudaEventDisableTiming);
        cudaEventCreateWithFlags(&evPrep, cudaEventDisableTiming);
        cudaEventCreateWithFlags(&evZ1, cudaEventDisableTiming);
        for (int i = 0; i < 3; i++) {
            cudaEventCreateWithFlags(&evGT[i], cudaEventDisableTiming);
            cudaEventCreateWithFlags(&evGM[i], cudaEventDisableTiming);
        }
        s_init = true;
    }

    const float* x_m = (const float*)d_in[0];
    const float* x_t = (const float*)d_in[1];
    const float* Wl  = (const float*)d_in[2];
    const float* bl  = (const float*)d_in[3];
    const float* Wr  = (const float*)d_in[4];
    const void*  e_mt = d_in[5];
    const void*  e_tm = d_in[6];
    float* out = (float*)d_out;

    float *inv_t, *inv_m;
    __half *x16m, *x16t, *agg_t, *agg_m, *bm0, *bm1, *bt0, *bt1;
    uint32_t* Bext;
    int *e32_mt, *e32_tm;
    cudaGetSymbolAddress((void**)&x16m, g_x16_m);
    cudaGetSymbolAddress((void**)&x16t, g_x16_t);
    cudaGetSymbolAddress((void**)&agg_t, g_agg_t);
    cudaGetSymbolAddress((void**)&agg_m, g_agg_m);
    cudaGetSymbolAddress((void**)&bm0, g_bm0);
    cudaGetSymbolAddress((void**)&bm1, g_bm1);
    cudaGetSymbolAddress((void**)&bt0, g_bt0);
    cudaGetSymbolAddress((void**)&bt1, g_bt1);
    cudaGetSymbolAddress((void**)&inv_t, g_inv_t);
    cudaGetSymbolAddress((void**)&inv_m, g_inv_m);
    cudaGetSymbolAddress((void**)&Bext, g_Bext);
    cudaGetSymbolAddress((void**)&e32_mt, g_e32_mt);
    cudaGetSymbolAddress((void**)&e32_tm, g_e32_tm);

    const int scatterBlocks = CDIV(NE, 8 * EPW);
    const int aggh4 = (int)AGGH4;
    __half* aggT[2] = { agg_t, agg_t + AGGH4 * 8 };
    __half* aggM[2] = { agg_m, agg_m + AGGH4 * 8 };
    float* out_m = out;
    float* out_t = out + (size_t)NM * DD;

    // ---- origin stream (track chain); prefix shape keeps ncu on scatter ----
    prep_buffers<<<4096, 256>>>((const float2*)x_m, (const float2*)x_t,
                                (half2*)x16m, (half2*)x16t,
                                (float4*)inv_t, (float4*)inv_m,
                                (float4*)aggT[0], (float4*)aggM[0]);
    cudaEventRecord(evZ, 0);
    detect_kernel<<<256, 256>>>((const unsigned*)e_mt);
    cudaEventRecord(evDet, 0);
    convert_count<<<CDIV(2 * NE, 256), 256>>>(e_mt, e32_mt, (float*)inv_t);
    scatter_bulk<<<scatterBlocks, 256>>>(x16m, e32_mt, aggT[0]);
    invert_kernel<<<CDIV(NT, 256), 256>>>((float*)inv_t, NT);
    prep_weights<<<CDIV(3 * 2 * KP2 * DD, 256), 256>>>(Wl, Wr, Bext);
    cudaEventRecord(evPrep, 0);
    gemm_sage_tc<<<CDIV(NT, 128), 256>>>(
        aggT[0], (float*)inv_t, x16t, Bext + (size_t)0 * KP2 * DD,
        bl + (size_t)0 * DD, bt0, NT, 1, 1);
    cudaEventRecord(evGT[0], 0);
    zero_kernel<<<2048, 256>>>((float4*)aggT[0], aggh4);

    // ---- stream M (musician chain) ----
    cudaStreamWaitEvent(sM, evDet, 0);
    cudaStreamWaitEvent(sM, evZ, 0);
    convert_count<<<CDIV(2 * NE, 256), 256, 0, sM>>>(e_tm, e32_tm, (float*)inv_m);
    invert_kernel<<<CDIV(NM, 256), 256, 0, sM>>>((float*)inv_m, NM);
    zero_two<<<2048, 256, 0, sM>>>((float4*)aggT[1], aggh4, (float4*)aggM[1], aggh4);
    cudaEventRecord(evZ1, sM);
    scatter_bulk<<<scatterBlocks, 256, 0, sM>>>(x16t, e32_tm, aggM[0]);
    cudaStreamWaitEvent(sM, evPrep, 0);
    gemm_sage_tc<<<CDIV(NM, 128), 256, 0, sM>>>(
        aggM[0], (float*)inv_m, x16m, Bext + (size_t)1 * KP2 * DD,
        bl + (size_t)1 * DD, bm0, NM, 1, 1);
    cudaEventRecord(evGM[0], sM);
    zero_kernel<<<2048, 256, 0, sM>>>((float4*)aggM[0], aggh4);

    const __half* xm_cur = bm0;
    const __half* xt_cur = bt0;

    for (int layer = 1; layer < 3; layer++) {
        const int b = layer & 1;
        void* xt_next = (layer == 2) ? (void*)out_t : (void*)bt1;
        void* xm_next = (layer == 2) ? (void*)out_m : (void*)bm1;
        int relu = (layer < 2) ? 1 : 0;
        int oh = (layer < 2) ? 1 : 0;

        cudaStreamWaitEvent(0, evGM[layer - 1], 0);
        if (layer == 1) cudaStreamWaitEvent(0, evZ1, 0);
        scatter_bulk<<<scatterBlocks, 256>>>(xm_cur, e32_mt, aggT[b]);
        gemm_sage_tc<<<CDIV(NT, 128), 256>>>(
            aggT[b], (float*)inv_t, xt_cur,
            Bext + (size_t)(layer * 2 + 0) * KP2 * DD,
            bl + (size_t)(layer * 2 + 0) * DD,
            xt_next, NT, relu, oh);
        cudaEventRecord(evGT[layer], 0);

        cudaStreamWaitEvent(sM, evGT[layer - 1], 0);
        scatter_bulk<<<scatterBlocks, 256, 0, sM>>>(xt_cur, e32_tm, aggM[b]);
        gemm_sage_tc<<<CDIV(NM, 128), 256, 0, sM>>>(
            aggM[b], (float*)inv_m, xm_cur,
            Bext + (size_t)(layer * 2 + 1) * KP2 * DD,
            bl + (size_t)(layer * 2 + 1) * DD,
            xm_next, NM, relu, oh);
        cudaEventRecord(evGM[layer], sM);

        xm_cur = (const __half*)xm_next;
        xt_cur = (const __half*)xt_next;
    }

    cudaStreamWaitEvent(0, evGM[2], 0);
}